// round 11
// baseline (speedup 1.0000x reference)
#include <cuda_runtime.h>
#include <cuda_bf16.h>
#include <cstdint>

#define B_    16
#define CIN_  512
#define COUT_ 3
#define WDIM_ 512
#define HW_   16384
#define HW4_  4096

#define FC_GAIN_     0.044194173824159216f
#define WEIGHT_GAIN_ 0.044194173824159216f
#define CLAMP_       256.0f

#define CHUNK_   8
#define NCHUNK_  (CIN_ / CHUNK_)
#define NBLOCKS_ (B_ * (HW4_ / 64))   // 1024

// Per-sample modulated 1x1 conv weights: [B][CIN] x float4 (w_o0, w_o1, w_o2, pad)
__device__ float4 g_wmod[B_ * CIN_];
__device__ unsigned g_count[B_] = {};  // per-batch styles blocks published
__device__ unsigned g_done = 0;        // blocks finished (graph-replay reset)

__device__ __forceinline__ void cp_async16(uint32_t smem_addr, const void* gptr) {
    asm volatile("cp.async.cg.shared.global [%0], [%1], 16;"
                 :: "r"(smem_addr), "l"(gptr) : "memory");
}

// ---------------------------------------------------------------------------
// Fused kernel, grid = 1024 x 64. Self-service styles + per-batch barriers:
// block (b,pix) computes styles for ITS OWN channels c = pix*8..pix*8+7 of
// ITS OWN batch b, so batch b's styles come exactly from the 64 blocks that
// consume them -> barrier couples only 64 blocks (count[b]==64), releases
// stagger per batch instead of a global max over all SM queues.
// smem 26 KB -> 8 blocks/SM, 1184 slots >= 1024: full co-residency.
// ---------------------------------------------------------------------------
__global__ __launch_bounds__(64)
void fused_kernel(const float* __restrict__ x,
                  const float* __restrict__ w,
                  const float* __restrict__ aW,
                  const float* __restrict__ ab,
                  const float* __restrict__ cw,
                  const float* __restrict__ cb,
                  float* __restrict__ out) {
    const int bid = blockIdx.x;
    const int t   = threadIdx.x;
    const int b   = bid >> 6;
    const int pix = bid & 63;
    const int p   = pix * 64 + t;                 // float4 pixel index

    __shared__ float4 swm[CIN_];
    __shared__ float4 stage[2][CHUNK_][64];
    __shared__ float4 ws[WDIM_ / 4];              // w[b], 2 KB

    const float4* __restrict__ xb =
        reinterpret_cast<const float4*>(x) + (size_t)b * CIN_ * HW4_ + p;
    const uint32_t stbase = (uint32_t)__cvta_generic_to_shared(&stage[0][0][t]);

    const int warp = t >> 5;
    const int lane = t & 31;
    const int c0   = pix * 8 + warp * 4;          // this warp's 4 channels

    // ---- 1) issue styles-critical loads first (per-SM queue head) ----
    {   // w[b] -> smem (2 float4 per thread)
        const float4* __restrict__ w4 = reinterpret_cast<const float4*>(w + (size_t)b * WDIM_);
        ws[t]      = w4[t];
        ws[64 + t] = w4[64 + t];
    }
    // channel c0 rows -> registers
    float4 Ac[3][4], An[3][4];
#pragma unroll
    for (int i = 0; i < 4; i++) {
        const int j = i * 32 + lane;
        Ac[0][i] = reinterpret_cast<const float4*>(aW + (size_t)(0 * CIN_ + c0) * WDIM_)[j];
        Ac[1][i] = reinterpret_cast<const float4*>(aW + (size_t)(1 * CIN_ + c0) * WDIM_)[j];
        Ac[2][i] = reinterpret_cast<const float4*>(aW + (size_t)(2 * CIN_ + c0) * WDIM_)[j];
    }

    // ---- 2) conv prefetch: chunks 0,1 -> buffers 0,1 (two groups) ----
#pragma unroll
    for (int i = 0; i < CHUNK_; i++)
        cp_async16(stbase + i * 1024, xb + (size_t)i * HW4_);
    asm volatile("cp.async.commit_group;" ::: "memory");
#pragma unroll
    for (int i = 0; i < CHUNK_; i++)
        cp_async16(stbase + (CHUNK_ * 1024) + i * 1024,
                   xb + (size_t)(CHUNK_ + i) * HW4_);
    asm volatile("cp.async.commit_group;" ::: "memory");

    __syncthreads();   // ws visible to both warps

    // ---- 3) styles for 4 channels per warp (software-pipelined) ----
#pragma unroll
    for (int cc = 0; cc < 4; cc++) {
        const int c = c0 + cc;
        if (cc < 3) {
            const int cn = c + 1;
#pragma unroll
            for (int i = 0; i < 4; i++) {
                const int j = i * 32 + lane;
                An[0][i] = reinterpret_cast<const float4*>(aW + (size_t)(0 * CIN_ + cn) * WDIM_)[j];
                An[1][i] = reinterpret_cast<const float4*>(aW + (size_t)(1 * CIN_ + cn) * WDIM_)[j];
                An[2][i] = reinterpret_cast<const float4*>(aW + (size_t)(2 * CIN_ + cn) * WDIM_)[j];
            }
        }

        float s0 = 0.f, s1 = 0.f, s2 = 0.f;
#pragma unroll
        for (int i = 0; i < 4; i++) {
            float4 wv = ws[i * 32 + lane];
            s0 += wv.x * Ac[0][i].x + wv.y * Ac[0][i].y + wv.z * Ac[0][i].z + wv.w * Ac[0][i].w;
            s1 += wv.x * Ac[1][i].x + wv.y * Ac[1][i].y + wv.z * Ac[1][i].z + wv.w * Ac[1][i].w;
            s2 += wv.x * Ac[2][i].x + wv.y * Ac[2][i].y + wv.z * Ac[2][i].z + wv.w * Ac[2][i].w;
        }
#pragma unroll
        for (int off = 16; off > 0; off >>= 1) {
            s0 += __shfl_xor_sync(0xFFFFFFFF, s0, off);
            s1 += __shfl_xor_sync(0xFFFFFFFF, s1, off);
            s2 += __shfl_xor_sync(0xFFFFFFFF, s2, off);
        }
        if (lane == 0) {
            float m1 = s0 * FC_GAIN_ + ab[0 * CIN_ + c];
            float m2 = s1 * FC_GAIN_ + ab[1 * CIN_ + c];
            float m3 = s2 * FC_GAIN_ + ab[2 * CIN_ + c];
            float st = (m1 * m2 + m3) * WEIGHT_GAIN_;
            g_wmod[b * CIN_ + c] = make_float4(cw[0 * CIN_ + c] * st,
                                               cw[1 * CIN_ + c] * st,
                                               cw[2 * CIN_ + c] * st,
                                               0.f);
        }

        if (cc < 3) {
#pragma unroll
            for (int r = 0; r < 3; r++)
#pragma unroll
                for (int i = 0; i < 4; i++)
                    Ac[r][i] = An[r][i];
        }
    }

    __syncthreads();
    if (t == 0) {
        __threadfence();
        atomicAdd(&g_count[b], 1u);
    }

    // ---- 4) per-batch barrier (64 blocks), then load swm ----
    if (t == 0) {
        unsigned v;
        do {
            asm volatile("ld.acquire.gpu.global.u32 %0, [%1];"
                         : "=r"(v) : "l"(&g_count[b]) : "memory");
        } while (v < 64u);
    }
    __syncthreads();

    {
        const float4* gw = g_wmod + b * CIN_;
#pragma unroll
        for (int i = 0; i < CIN_ / 64; i++)
            swm[i * 64 + t] = gw[i * 64 + t];
    }
    __syncthreads();

    // ---- 5) conv main loop: chunk k in buf[k&1]; after consuming k,
    //         refill buf[k&1] with chunk k+2. wait_group 1 => chunk k ready.
    float4 a0 = make_float4(0.f, 0.f, 0.f, 0.f);
    float4 a1 = a0;
    float4 a2 = a0;

    for (int k = 0; k < NCHUNK_; k++) {
        const int cur = k & 1;
        if (k + 1 < NCHUNK_) {
            asm volatile("cp.async.wait_group 1;" ::: "memory");
        } else {
            asm volatile("cp.async.wait_group 0;" ::: "memory");
        }

#pragma unroll
        for (int i = 0; i < CHUNK_; i++) {
            float4 xv = stage[cur][i][t];
            float4 wm = swm[k * CHUNK_ + i];
            a0.x = fmaf(xv.x, wm.x, a0.x);
            a0.y = fmaf(xv.y, wm.x, a0.y);
            a0.z = fmaf(xv.z, wm.x, a0.z);
            a0.w = fmaf(xv.w, wm.x, a0.w);
            a1.x = fmaf(xv.x, wm.y, a1.x);
            a1.y = fmaf(xv.y, wm.y, a1.y);
            a1.z = fmaf(xv.z, wm.y, a1.z);
            a1.w = fmaf(xv.w, wm.y, a1.w);
            a2.x = fmaf(xv.x, wm.z, a2.x);
            a2.y = fmaf(xv.y, wm.z, a2.y);
            a2.z = fmaf(xv.z, wm.z, a2.z);
            a2.w = fmaf(xv.w, wm.z, a2.w);
        }

        if (k + 2 < NCHUNK_) {
            const int c2 = (k + 2) * CHUNK_;
            const uint32_t sb = stbase + cur * (CHUNK_ * 1024);
#pragma unroll
            for (int i = 0; i < CHUNK_; i++)
                cp_async16(sb + i * 1024, xb + (size_t)(c2 + i) * HW4_);
            asm volatile("cp.async.commit_group;" ::: "memory");
        }
    }

    const float b0 = cb[0], b1 = cb[1], b2 = cb[2];

    a0.x = fminf(fmaxf(a0.x + b0, -CLAMP_), CLAMP_);
    a0.y = fminf(fmaxf(a0.y + b0, -CLAMP_), CLAMP_);
    a0.z = fminf(fmaxf(a0.z + b0, -CLAMP_), CLAMP_);
    a0.w = fminf(fmaxf(a0.w + b0, -CLAMP_), CLAMP_);

    a1.x = fminf(fmaxf(a1.x + b1, -CLAMP_), CLAMP_);
    a1.y = fminf(fmaxf(a1.y + b1, -CLAMP_), CLAMP_);
    a1.z = fminf(fmaxf(a1.z + b1, -CLAMP_), CLAMP_);
    a1.w = fminf(fmaxf(a1.w + b1, -CLAMP_), CLAMP_);

    a2.x = fminf(fmaxf(a2.x + b2, -CLAMP_), CLAMP_);
    a2.y = fminf(fmaxf(a2.y + b2, -CLAMP_), CLAMP_);
    a2.z = fminf(fmaxf(a2.z + b2, -CLAMP_), CLAMP_);
    a2.w = fminf(fmaxf(a2.w + b2, -CLAMP_), CLAMP_);

    float4* __restrict__ o =
        reinterpret_cast<float4*>(out) + (size_t)b * COUT_ * HW4_ + p;
    o[0 * HW4_] = a0;
    o[1 * HW4_] = a1;
    o[2 * HW4_] = a2;

    // ---- reset counters for next graph replay (last block out) ----
    __syncthreads();
    if (t == 0) {
        __threadfence();
        unsigned d = atomicAdd(&g_done, 1u);
        if (d == NBLOCKS_ - 1) {
#pragma unroll
            for (int i = 0; i < B_; i++)
                g_count[i] = 0;
            g_done = 0;
            __threadfence();
        }
    }
}

// ---------------------------------------------------------------------------
// inputs (metadata order): x, w, affine_W, affine_b, conv_w, conv_b
// ---------------------------------------------------------------------------
extern "C" void kernel_launch(void* const* d_in, const int* in_sizes, int n_in,
                              void* d_out, int out_size) {
    const float* x  = (const float*)d_in[0];
    const float* w  = (const float*)d_in[1];
    const float* aW = (const float*)d_in[2];
    const float* ab = (const float*)d_in[3];
    const float* cw = (const float*)d_in[4];
    const float* cb = (const float*)d_in[5];
    float* out = (float*)d_out;

    fused_kernel<<<NBLOCKS_, 64>>>(x, w, aW, ab, cw, cb, out);
}